// round 15
// baseline (speedup 1.0000x reference)
#include <cuda_runtime.h>
#include <cuda_fp16.h>
#include <cstdint>

#define B_   16
#define C_   4
#define HH   256
#define WW   256
#define HID  64
#define PCH  116          // C_*(3*10-1)
#define HW   (HH*WW)      // 65536

// ---------------- device scratch (no allocations allowed) ----------------
// hid as packed fp16x2, ic-contiguous per pixel: g_hidF[px*32 + p] = ic 2p,2p+1
__device__ __align__(16) uint32_t g_hidF[B_ * HW * 32];    // 134 MB
__device__ float g_partial[B_ * 256];
// W2 fragments, 128B-blocked: off = chunk*1024 + ng*256 + p*128 + lane*4 + h*2 + w
__device__ __align__(16) uint32_t g_Wf2[288 * 128];
// W1 in mma.m16n8k8 B-fragment layout, fp16
__device__ __align__(16) uint32_t g_Wf1[6 * 8 * 32];

// ======================= helpers =====================
__device__ __forceinline__ uint32_t smem_to_u32(const void* p) {
    uint32_t a;
    asm("{ .reg .u64 t; cvta.to.shared.u64 t, %1; cvt.u32.u64 %0, t; }"
        : "=r"(a) : "l"(p));
    return a;
}
#define SMEM_SWIZZLE_128B(o) ((o) ^ (((o) >> 3) & 0x70))

__device__ __forceinline__ void cp_async16(uint32_t saddr, const void* gptr,
                                           int src_bytes) {
    asm volatile("cp.async.cg.shared.global [%0], [%1], 16, %2;"
        :: "r"(saddr), "l"(gptr), "r"(src_bytes));
}
#define CP_COMMIT() asm volatile("cp.async.commit_group;" ::: "memory")
#define CP_WAIT0()  asm volatile("cp.async.wait_group 0;" ::: "memory")

__device__ __forceinline__ void ldsm_x4(uint32_t* r, uint32_t addr) {
    asm volatile("ldmatrix.sync.aligned.m8n8.x4.shared.b16 {%0,%1,%2,%3}, [%4];"
        : "=r"(r[0]), "=r"(r[1]), "=r"(r[2]), "=r"(r[3]) : "r"(addr));
}
// f16-accumulator MMA: D(f16x2 pair) += A*B
__device__ __forceinline__ void mma_f16a(uint32_t* d, const uint32_t* a,
                                         const uint32_t* b) {
    asm volatile(
        "mma.sync.aligned.m16n8k16.row.col.f16.f16.f16.f16 "
        "{%0,%1}, {%2,%3,%4,%5}, {%6,%7}, {%0,%1};"
        : "+r"(d[0]), "+r"(d[1])
        : "r"(a[0]), "r"(a[1]), "r"(a[2]), "r"(a[3]),
          "r"(b[0]), "r"(b[1]));
}
__device__ __forceinline__ void mma_f16_k8(float* d, const uint32_t* a,
                                           uint32_t b) {
    asm volatile(
        "mma.sync.aligned.m16n8k8.row.col.f32.f16.f16.f32 "
        "{%0,%1,%2,%3}, {%4,%5}, {%6}, {%0,%1,%2,%3};"
        : "+f"(d[0]), "+f"(d[1]), "+f"(d[2]), "+f"(d[3])
        : "r"(a[0]), "r"(a[1]), "r"(b));
}

// =========================================================================
// prep_w1: pack W1 into m16n8k8 B-fragment layout, fp16.
// =========================================================================
__global__ void __launch_bounds__(256) prep_w1_kernel(const float* __restrict__ W1)
{
    const int i = blockIdx.x * 256 + threadIdx.x;
    if (i >= 6 * 8 * 32) return;
    const int lane  = i & 31;
    const int nt    = (i >> 5) & 7;
    const int chunk = i >> 8;
    const int ky = chunk >> 1, cb = chunk & 1;
    const int n  = nt * 8 + (lane >> 2);
    const int k0 = (lane & 3) * 2;

    float w[2];
    #pragma unroll
    for (int e = 0; e < 2; ++e) {
        const int ke = k0 + e;
        const int p = ke >> 2, ic = ke & 3;
        const int kx = cb ? (2 + p) : p;
        w[e] = (kx < 3) ? W1[n * 36 + ic * 9 + ky * 3 + kx] : 0.f;
    }
    const __half2 h = __floats2half2_rn(w[0], w[1]);
    g_Wf1[i] = *(const uint32_t*)&h;
}

// =========================================================================
// conv1 via HMMA fp16: clean -> relu(conv3x3) -> g_hidF (packed fp16).
// =========================================================================
__global__ void __launch_bounds__(256) conv1_tc_kernel(
    const float* __restrict__ clean,
    const float* __restrict__ b1)
{
    __shared__ uint2 s_cl[3][132];
    __shared__ float s_b1[64];
    const int tid = threadIdx.x, wid = tid >> 5, lane = tid & 31;
    const int x0 = blockIdx.x * 128;
    const int y  = blockIdx.y;
    const int b  = blockIdx.z;
    const int mg = wid & 3;
    const int ng = wid >> 2;

    if (tid < 64) s_b1[tid] = b1[tid];
    for (int i = tid; i < 3 * 131; i += 256) {
        const int ky = i / 131, s = i - ky * 131;
        const int yy = y + ky - 1, xx = x0 + s - 1;
        uint2 v = make_uint2(0, 0);
        if ((unsigned)yy < 256u && (unsigned)xx < 256u) {
            const int base = (b * 4) * HW + yy * WW + xx;
            const float c0 = clean[base];
            const float c1 = clean[base + HW];
            const float c2 = clean[base + 2 * HW];
            const float c3 = clean[base + 3 * HW];
            const __half2 h01 = __floats2half2_rn(c0, c1);
            const __half2 h23 = __floats2half2_rn(c2, c3);
            v.x = *(const uint32_t*)&h01;
            v.y = *(const uint32_t*)&h23;
        }
        s_cl[ky][s] = v;
    }
    __syncthreads();

    float d[2][4][4];
    #pragma unroll
    for (int mt = 0; mt < 2; ++mt)
        #pragma unroll
        for (int nt = 0; nt < 4; ++nt)
            #pragma unroll
            for (int r = 0; r < 4; ++r) d[mt][nt][r] = 0.f;

    const uint32_t sbcl = smem_to_u32(&s_cl[0][0]);
    const int q = lane & 3;
    #pragma unroll
    for (int chunk = 0; chunk < 6; ++chunk) {
        const int ky = chunk >> 1, cb = chunk & 1;
        const int so = (cb ? 2 : 0) + (q >> 1);
        uint32_t a[2][2];
        #pragma unroll
        for (int mt = 0; mt < 2; ++mt) {
            const int row = mg * 32 + mt * 16 + (lane >> 2);
            const uint32_t ad = sbcl + (uint32_t)((ky * 132 + row + so) * 8 + (q & 1) * 4);
            asm volatile("ld.shared.b32 %0, [%1];" : "=r"(a[mt][0]) : "r"(ad));
            asm volatile("ld.shared.b32 %0, [%1];" : "=r"(a[mt][1]) : "r"(ad + 64));
        }
        #pragma unroll
        for (int nt = 0; nt < 4; ++nt) {
            const uint32_t bw = g_Wf1[(chunk * 8 + ng * 4 + nt) * 32 + lane];
            #pragma unroll
            for (int mt = 0; mt < 2; ++mt)
                mma_f16_k8(d[mt][nt], a[mt], bw);
        }
    }

    #pragma unroll
    for (int mt = 0; mt < 2; ++mt) {
        const int r0 = mg * 32 + mt * 16 + (lane >> 2);
        const size_t px0 = (size_t)(b * HH + y) * WW + x0 + r0;
        #pragma unroll
        for (int nt = 0; nt < 4; ++nt) {
            const int col = ng * 32 + nt * 8 + (lane & 3) * 2;
            const float bb0 = s_b1[col], bb1 = s_b1[col + 1];
            const __half2 h0 = __floats2half2_rn(fmaxf(d[mt][nt][0] + bb0, 0.f),
                                                 fmaxf(d[mt][nt][1] + bb1, 0.f));
            const __half2 h1 = __floats2half2_rn(fmaxf(d[mt][nt][2] + bb0, 0.f),
                                                 fmaxf(d[mt][nt][3] + bb1, 0.f));
            const int word = col >> 1;
            g_hidF[px0 * 32 + word]       = *(const uint32_t*)&h0;
            g_hidF[(px0 + 8) * 32 + word] = *(const uint32_t*)&h1;
        }
    }
}

// =========================================================================
// prep_w: pack W2 into 128B-blocked mma B-fragment layout, fp16.
// =========================================================================
__global__ void __launch_bounds__(256) prep_w_kernel(const float* __restrict__ W2)
{
    const int o = blockIdx.x * 256 + threadIdx.x;
    if (o >= 288 * 128) return;
    const int w    = o & 1;
    const int h    = (o >> 1) & 1;
    const int lane = (o >> 2) & 31;
    const int blk  = o >> 7;
    const int p    = blk & 1;
    const int ngc  = blk >> 1;
    const int ng   = ngc & 3;
    const int chunk = ngc >> 2;        // 0..35 = j*4+ks
    const int j    = chunk >> 2;
    const int ks   = chunk & 3;
    const int nt   = ng * 4 + p * 2 + h;
    const int n    = nt * 8 + (lane >> 2);
    const int ic0  = ks * 16 + w * 8 + (lane & 3) * 2;

    float w0 = 0.f, w1 = 0.f;
    if (n < PCH) {
        w0 = W2[n * 576 + ic0 * 9 + j];
        w1 = W2[n * 576 + (ic0 + 1) * 9 + j];
    }
    const __half h0 = __float2half_rn(w0), h1 = __float2half_rn(w1);
    const uint16_t uh0 = *(const uint16_t*)&h0, uh1 = *(const uint16_t*)&h1;
    g_Wf2[o] = (uint32_t)uh0 | ((uint32_t)uh1 << 16);
}

// =========================================================================
// fused conv2 (HMMA fp16, f16 accumulators) + bias + spline + lad reduction.
// CTA = 2-row tile (M=256) x 128 oc padded. 512 threads / 16 warps,
// 2 CTAs/SM (64 regs target). B fragments via LDG.128 from global.
// Epilogue in 2 channel-pair passes (58 oc-rows staged, reusing A smem).
// =========================================================================
#define PLANE_B  16640                 // 130 slots * 128 B
#define SMEM_TC  66560                 // 4 A planes (s_out 58*264*4 reuses)

__device__ __forceinline__ float softplus_fast(float t) {
    return fmaxf(t, 0.f) + __logf(1.f + __expf(-fabsf(t)));
}

__global__ void __launch_bounds__(512, 2) conv2_fused_kernel(
    const float* __restrict__ b2,
    const float* __restrict__ xin,
    float* __restrict__ out)
{
    extern __shared__ char smem[];
    __shared__ float s_b2[128];
    __shared__ float s_wr[16];
    const uint32_t sb = smem_to_u32(smem);
    const int tid = threadIdx.x, wid = tid >> 5, lane = tid & 31;
    const int x0 = blockIdx.x * 128;
    const int y0 = blockIdx.y * 2;
    const int b  = blockIdx.z;
    const int mg = wid & 3;            // m-group (64 rows of 256)
    const int ng = wid >> 2;           // n-group (32 cols of 128)

    if (tid < 128) s_b2[tid] = (tid < PCH) ? b2[tid] : 0.f;

    // ---- build 4 input-row planes (y0-1 .. y0+2) via cp.async ----
    for (int g = tid; g < 4 * 130 * 8; g += 512) {
        const int p = g / 1040, rem = g - p * 1040;
        const int s = rem >> 3, q = rem & 7;
        const int yy = y0 + p - 1, xx = x0 + s - 1;
        const bool ok = ((unsigned)yy < 256u) && ((unsigned)xx < 256u);
        const size_t px = ok ? ((size_t)(b * HH + yy) * WW + xx) : 0;
        const uint32_t sa = sb + p * PLANE_B
                          + SMEM_SWIZZLE_128B((uint32_t)(s * 128 + q * 16));
        cp_async16(sa, &g_hidF[px * 32 + q * 4], ok ? 16 : 0);
    }
    CP_COMMIT();
    CP_WAIT0();
    __syncthreads();

    // f16-packed accumulators: dacc[mt][nt4] = {rows r/r+8, cols 2c,2c+1}
    uint32_t dacc[4][4][2];
    #pragma unroll
    for (int mt = 0; mt < 4; ++mt)
        #pragma unroll
        for (int nt = 0; nt < 4; ++nt) { dacc[mt][nt][0] = 0u; dacc[mt][nt][1] = 0u; }

    // ---- MMA phase: 36 chunks (ky*12 + kx*4 + ks), barrier-free ----
    const uint32_t planeBase = sb + (mg >> 1) * PLANE_B;   // half-row offset
    const uint32_t* wPtr = g_Wf2 + ng * 256 + lane * 4;
    const uint32_t mBase = (uint32_t)((mg & 1) * 64 + (lane & 15));
    const uint32_t hsel  = (uint32_t)((lane >> 4) * 16);

    #pragma unroll
    for (int chunk = 0; chunk < 36; ++chunk) {
        const int ky = chunk / 12;
        const int kx = (chunk % 12) >> 2;
        const int ks = chunk & 3;
        const uint32_t pb = planeBase + ky * PLANE_B;
        const uint32_t cb = ks * 32 + hsel;
        uint32_t ah[4][4];
        #pragma unroll
        for (int mt = 0; mt < 4; ++mt) {
            const uint32_t row = mBase + mt * 16 + kx;
            ldsm_x4(ah[mt], pb + SMEM_SWIZZLE_128B(row * 128 + cb));
        }
        uint32_t bh[4][2];
        {
            const uint4 w0 = *(const uint4*)(wPtr + chunk * 1024);
            const uint4 w1 = *(const uint4*)(wPtr + chunk * 1024 + 128);
            bh[0][0] = w0.x; bh[0][1] = w0.y;
            bh[1][0] = w0.z; bh[1][1] = w0.w;
            bh[2][0] = w1.x; bh[2][1] = w1.y;
            bh[3][0] = w1.z; bh[3][1] = w1.w;
        }
        #pragma unroll
        for (int mt = 0; mt < 4; ++mt)
            #pragma unroll
            for (int nt4 = 0; nt4 < 4; ++nt4)
                mma_f16a(dacc[mt][nt4], ah[mt], bh[nt4]);
    }

    // ---- epilogue + spline in 2 channel-pair passes ----
    float* s_out = (float*)smem;       // [58 n-rows][m padded 264]
    float ladsum = 0.f;
    #pragma unroll
    for (int pass = 0; pass < 2; ++pass) {
        const int nlo = pass * 58;
        __syncthreads();               // previous smem contents consumed

        #pragma unroll
        for (int mt = 0; mt < 4; ++mt)
            #pragma unroll
            for (int nt4 = 0; nt4 < 4; ++nt4)
                #pragma unroll
                for (int g = 0; g < 2; ++g) {
                    const int n0 = ng * 32 + nt4 * 8 + (lane & 3) * 2;
                    if (n0 >= nlo && n0 < nlo + 58) {
                        const int m = mg * 64 + mt * 16 + (lane >> 2) + g * 8;
                        const __half2 h = *(const __half2*)&dacc[mt][nt4][g];
                        const float2 v = __half22float2(h);
                        s_out[(n0 - nlo) * 264 + m]     = v.x;
                        s_out[(n0 + 1 - nlo) * 264 + m] = v.y;
                    }
                }
        __syncthreads();

        // spline: 512 units = (c = pass*2 + tid>>8, m = tid&255)
        {
            const int m = tid & 255;
            const int c = pass * 2 + (tid >> 8);
            const int yr = y0 + (m >> 7);
            const int xc_ = x0 + (m & 127);
            float pv[29];
            #pragma unroll
            for (int j = 0; j < 29; j++)
                pv[j] = s_out[(c * 29 + j - nlo) * 264 + m] + s_b2[c * 29 + j];

            const float xv = xin[((b * C_ + c) * HW) + yr * WW + xc_];

            float uw[10];
            #pragma unroll
            for (int j = 0; j < 10; j++) uw[j] = pv[j] * 0.125f;
            float mw = uw[0];
            #pragma unroll
            for (int j = 1; j < 10; j++) mw = fmaxf(mw, uw[j]);
            float ew[10]; float ssum = 0.f;
            #pragma unroll
            for (int j = 0; j < 10; j++) { ew[j] = __expf(uw[j] - mw); ssum += ew[j]; }
            float inv = 1.0f / ssum;
            float cw[11]; cw[0] = -1.f;
            {
                float acc = 0.f;
                #pragma unroll
                for (int j = 0; j < 10; j++) {
                    float wj = fmaf(0.99f * inv, ew[j], 0.001f);
                    acc += wj;
                    cw[j + 1] = fmaf(2.f, acc, -1.f);
                }
            }
            cw[10] = 1.f;
            float wd[10];
            #pragma unroll
            for (int j = 0; j < 10; j++) wd[j] = cw[j + 1] - cw[j];

            float uh[10];
            #pragma unroll
            for (int j = 0; j < 10; j++) uh[j] = pv[10 + j] * 0.125f;
            float mh = uh[0];
            #pragma unroll
            for (int j = 1; j < 10; j++) mh = fmaxf(mh, uh[j]);
            float eh[10]; float hsum = 0.f;
            #pragma unroll
            for (int j = 0; j < 10; j++) { eh[j] = __expf(uh[j] - mh); hsum += eh[j]; }
            float hinv = 1.0f / hsum;
            float ch[11]; ch[0] = -1.f;
            {
                float acc = 0.f;
                #pragma unroll
                for (int j = 0; j < 10; j++) {
                    float hj = fmaf(0.99f * hinv, eh[j], 0.001f);
                    acc += hj;
                    ch[j + 1] = fmaf(2.f, acc, -1.f);
                }
            }
            ch[10] = 1.f;
            float hd[10];
            #pragma unroll
            for (int j = 0; j < 10; j++) hd[j] = ch[j + 1] - ch[j];

            const float spc = 0.53974215f;          // log(exp(0.999)-1)
            const float dvE = 0.001f + softplus_fast(spc);
            float dv[11];
            dv[0] = dvE; dv[10] = dvE;
            #pragma unroll
            for (int j = 1; j < 10; j++) dv[j] = 0.001f + softplus_fast(pv[19 + j]);

            const float xc = fminf(fmaxf(xv, -1.f), 1.f);
            float icw = cw[0], ibw = wd[0], ich = ch[0], ihh = hd[0];
            float d0 = dv[0], d1 = dv[1];
            #pragma unroll
            for (int k = 1; k < 10; k++) {
                if (xc >= cw[k]) {
                    icw = cw[k]; ibw = wd[k]; ich = ch[k]; ihh = hd[k];
                    d0 = dv[k]; d1 = dv[k + 1];
                }
            }

            const float idl   = ihh / ibw;
            const float theta = (xc - icw) / ibw;
            const float th2   = theta * theta;
            const float tt    = theta * (1.f - theta);
            const float numer = ihh * (idl * th2 + d0 * tt);
            const float denom = idl + (d0 + d1 - 2.f * idl) * tt;
            const float zin   = ich + numer / denom;
            const float omt   = 1.f - theta;
            const float dnum  = idl * idl * (d1 * th2 + 2.f * idl * tt + d0 * omt * omt);
            const float ladv  = __logf(dnum) - 2.f * __logf(denom);

            const bool inside = (xv >= -1.f) && (xv <= 1.f);
            out[((b * C_ + c) * HW) + yr * WW + xc_] = inside ? zin : xv;
            ladsum += inside ? ladv : 0.f;
        }
    }

    // ---- deterministic block reduction of ladsum ----
    #pragma unroll
    for (int off = 16; off; off >>= 1)
        ladsum += __shfl_down_sync(0xffffffffu, ladsum, off);
    if (lane == 0) s_wr[wid] = ladsum;
    __syncthreads();
    if (tid == 0) {
        float s = 0.f;
        #pragma unroll
        for (int i = 0; i < 16; i++) s += s_wr[i];
        g_partial[(b * 128 + blockIdx.y) * 2 + blockIdx.x] = s;
    }
}

// =========================================================================
__global__ void __launch_bounds__(256) reduce_kernel(float* __restrict__ out)
{
    const int b = blockIdx.x;
    const int tid = threadIdx.x;
    __shared__ double sd[256];
    sd[tid] = (double)g_partial[b * 256 + tid];
    __syncthreads();
    for (int off = 128; off; off >>= 1) {
        if (tid < off) sd[tid] += sd[tid + off];
        __syncthreads();
    }
    if (tid == 0) out[B_ * C_ * HW + b] = (float)sd[0];
}

// =========================================================================
extern "C" void kernel_launch(void* const* d_in, const int* in_sizes, int n_in,
                              void* d_out, int out_size)
{
    const float* x     = (const float*)d_in[0];
    const float* clean = (const float*)d_in[1];
    const float* W1    = (const float*)d_in[2];
    const float* b1    = (const float*)d_in[3];
    const float* W2    = (const float*)d_in[4];
    const float* b2    = (const float*)d_in[5];
    float* out = (float*)d_out;

    cudaFuncSetAttribute(conv2_fused_kernel,
                         cudaFuncAttributeMaxDynamicSharedMemorySize, SMEM_TC);

    prep_w1_kernel<<<6, 256>>>(W1);
    prep_w_kernel<<<144, 256>>>(W2);
    conv1_tc_kernel<<<dim3(2, 256, 16), 256>>>(clean, b1);
    conv2_fused_kernel<<<dim3(2, 128, 16), 512, SMEM_TC>>>(b2, x, out);
    reduce_kernel<<<16, 256>>>(out);
}

// round 16
// speedup vs baseline: 1.0064x; 1.0064x over previous
#include <cuda_runtime.h>
#include <cuda_fp16.h>
#include <cstdint>

#define B_   16
#define C_   4
#define HH   256
#define WW   256
#define HID  64
#define PCH  116          // C_*(3*10-1)
#define HW   (HH*WW)      // 65536

// ---------------- device scratch (no allocations allowed) ----------------
// hid as packed fp16x2, ic-contiguous per pixel: g_hidF[px*32 + p] = ic 2p,2p+1
__device__ __align__(16) uint32_t g_hidF[B_ * HW * 32];    // 134 MB
__device__ float g_partial[B_ * 256];
// W2 fragments, LDS.128-blocked: blk = (chunk*4+ng)*2+p, word = lane*4+h*2+w
__device__ __align__(16) uint32_t g_Wf2[288 * 128];
// W1 in mma.m16n8k8 B-fragment layout, fp16
__device__ __align__(16) uint32_t g_Wf1[6 * 8 * 32];

// ======================= helpers =====================
__device__ __forceinline__ uint32_t smem_to_u32(const void* p) {
    uint32_t a;
    asm("{ .reg .u64 t; cvta.to.shared.u64 t, %1; cvt.u32.u64 %0, t; }"
        : "=r"(a) : "l"(p));
    return a;
}
#define SMEM_SWIZZLE_128B(o) ((o) ^ (((o) >> 3) & 0x70))

__device__ __forceinline__ void cp_async16(uint32_t saddr, const void* gptr,
                                           int src_bytes) {
    asm volatile("cp.async.cg.shared.global [%0], [%1], 16, %2;"
        :: "r"(saddr), "l"(gptr), "r"(src_bytes));
}
#define CP_COMMIT() asm volatile("cp.async.commit_group;" ::: "memory")
#define CP_WAIT0()  asm volatile("cp.async.wait_group 0;" ::: "memory")

__device__ __forceinline__ void ldsm_x4(uint32_t* r, uint32_t addr) {
    asm volatile("ldmatrix.sync.aligned.m8n8.x4.shared.b16 {%0,%1,%2,%3}, [%4];"
        : "=r"(r[0]), "=r"(r[1]), "=r"(r[2]), "=r"(r[3]) : "r"(addr));
}
__device__ __forceinline__ void lds128(uint32_t* r, uint32_t addr) {
    asm volatile("ld.shared.v4.b32 {%0,%1,%2,%3}, [%4];"
        : "=r"(r[0]), "=r"(r[1]), "=r"(r[2]), "=r"(r[3]) : "r"(addr));
}
__device__ __forceinline__ void mma_f16(float* d, const uint32_t* a,
                                        const uint32_t* b) {
    asm volatile(
        "mma.sync.aligned.m16n8k16.row.col.f32.f16.f16.f32 "
        "{%0,%1,%2,%3}, {%4,%5,%6,%7}, {%8,%9}, {%0,%1,%2,%3};"
        : "+f"(d[0]), "+f"(d[1]), "+f"(d[2]), "+f"(d[3])
        : "r"(a[0]), "r"(a[1]), "r"(a[2]), "r"(a[3]),
          "r"(b[0]), "r"(b[1]));
}
__device__ __forceinline__ void mma_f16_k8(float* d, const uint32_t* a,
                                           uint32_t b) {
    asm volatile(
        "mma.sync.aligned.m16n8k8.row.col.f32.f16.f16.f32 "
        "{%0,%1,%2,%3}, {%4,%5}, {%6}, {%0,%1,%2,%3};"
        : "+f"(d[0]), "+f"(d[1]), "+f"(d[2]), "+f"(d[3])
        : "r"(a[0]), "r"(a[1]), "r"(b));
}

// =========================================================================
// prep_w1: pack W1 into m16n8k8 B-fragment layout, fp16.
// =========================================================================
__global__ void __launch_bounds__(256) prep_w1_kernel(const float* __restrict__ W1)
{
    const int i = blockIdx.x * 256 + threadIdx.x;
    if (i >= 6 * 8 * 32) return;
    const int lane  = i & 31;
    const int nt    = (i >> 5) & 7;
    const int chunk = i >> 8;
    const int ky = chunk >> 1, cb = chunk & 1;
    const int n  = nt * 8 + (lane >> 2);
    const int k0 = (lane & 3) * 2;

    float w[2];
    #pragma unroll
    for (int e = 0; e < 2; ++e) {
        const int ke = k0 + e;
        const int p = ke >> 2, ic = ke & 3;
        const int kx = cb ? (2 + p) : p;
        w[e] = (kx < 3) ? W1[n * 36 + ic * 9 + ky * 3 + kx] : 0.f;
    }
    const __half2 h = __floats2half2_rn(w[0], w[1]);
    g_Wf1[i] = *(const uint32_t*)&h;
}

// =========================================================================
// conv1 via HMMA fp16: clean -> relu(conv3x3) -> g_hidF (packed fp16).
// =========================================================================
__global__ void __launch_bounds__(256) conv1_tc_kernel(
    const float* __restrict__ clean,
    const float* __restrict__ b1)
{
    __shared__ uint2 s_cl[3][132];
    __shared__ float s_b1[64];
    const int tid = threadIdx.x, wid = tid >> 5, lane = tid & 31;
    const int x0 = blockIdx.x * 128;
    const int y  = blockIdx.y;
    const int b  = blockIdx.z;
    const int mg = wid & 3;
    const int ng = wid >> 2;

    if (tid < 64) s_b1[tid] = b1[tid];
    for (int i = tid; i < 3 * 131; i += 256) {
        const int ky = i / 131, s = i - ky * 131;
        const int yy = y + ky - 1, xx = x0 + s - 1;
        uint2 v = make_uint2(0, 0);
        if ((unsigned)yy < 256u && (unsigned)xx < 256u) {
            const int base = (b * 4) * HW + yy * WW + xx;
            const float c0 = clean[base];
            const float c1 = clean[base + HW];
            const float c2 = clean[base + 2 * HW];
            const float c3 = clean[base + 3 * HW];
            const __half2 h01 = __floats2half2_rn(c0, c1);
            const __half2 h23 = __floats2half2_rn(c2, c3);
            v.x = *(const uint32_t*)&h01;
            v.y = *(const uint32_t*)&h23;
        }
        s_cl[ky][s] = v;
    }
    __syncthreads();

    float d[2][4][4];
    #pragma unroll
    for (int mt = 0; mt < 2; ++mt)
        #pragma unroll
        for (int nt = 0; nt < 4; ++nt)
            #pragma unroll
            for (int r = 0; r < 4; ++r) d[mt][nt][r] = 0.f;

    const uint32_t sbcl = smem_to_u32(&s_cl[0][0]);
    const int q = lane & 3;
    #pragma unroll
    for (int chunk = 0; chunk < 6; ++chunk) {
        const int ky = chunk >> 1, cb = chunk & 1;
        const int so = (cb ? 2 : 0) + (q >> 1);
        uint32_t a[2][2];
        #pragma unroll
        for (int mt = 0; mt < 2; ++mt) {
            const int row = mg * 32 + mt * 16 + (lane >> 2);
            const uint32_t ad = sbcl + (uint32_t)((ky * 132 + row + so) * 8 + (q & 1) * 4);
            asm volatile("ld.shared.b32 %0, [%1];" : "=r"(a[mt][0]) : "r"(ad));
            asm volatile("ld.shared.b32 %0, [%1];" : "=r"(a[mt][1]) : "r"(ad + 64));
        }
        #pragma unroll
        for (int nt = 0; nt < 4; ++nt) {
            const uint32_t bw = g_Wf1[(chunk * 8 + ng * 4 + nt) * 32 + lane];
            #pragma unroll
            for (int mt = 0; mt < 2; ++mt)
                mma_f16_k8(d[mt][nt], a[mt], bw);
        }
    }

    #pragma unroll
    for (int mt = 0; mt < 2; ++mt) {
        const int r0 = mg * 32 + mt * 16 + (lane >> 2);
        const size_t px0 = (size_t)(b * HH + y) * WW + x0 + r0;
        #pragma unroll
        for (int nt = 0; nt < 4; ++nt) {
            const int col = ng * 32 + nt * 8 + (lane & 3) * 2;
            const float bb0 = s_b1[col], bb1 = s_b1[col + 1];
            const __half2 h0 = __floats2half2_rn(fmaxf(d[mt][nt][0] + bb0, 0.f),
                                                 fmaxf(d[mt][nt][1] + bb1, 0.f));
            const __half2 h1 = __floats2half2_rn(fmaxf(d[mt][nt][2] + bb0, 0.f),
                                                 fmaxf(d[mt][nt][3] + bb1, 0.f));
            const int word = col >> 1;
            g_hidF[px0 * 32 + word]       = *(const uint32_t*)&h0;
            g_hidF[(px0 + 8) * 32 + word] = *(const uint32_t*)&h1;
        }
    }
}

// =========================================================================
// prep_w: pack W2 into LDS.128-blocked mma B-fragment layout, fp16.
// =========================================================================
__global__ void __launch_bounds__(256) prep_w_kernel(const float* __restrict__ W2)
{
    const int o = blockIdx.x * 256 + threadIdx.x;
    if (o >= 288 * 128) return;
    const int w    = o & 1;
    const int h    = (o >> 1) & 1;
    const int lane = (o >> 2) & 31;
    const int blk  = o >> 7;
    const int p    = blk & 1;
    const int ngc  = blk >> 1;
    const int ng   = ngc & 3;
    const int chunk = ngc >> 2;        // 0..35 = j*4+ks
    const int j    = chunk >> 2;
    const int ks   = chunk & 3;
    const int nt   = ng * 4 + p * 2 + h;
    const int n    = nt * 8 + (lane >> 2);
    const int ic0  = ks * 16 + w * 8 + (lane & 3) * 2;

    float w0 = 0.f, w1 = 0.f;
    if (n < PCH) {
        w0 = W2[n * 576 + ic0 * 9 + j];
        w1 = W2[n * 576 + (ic0 + 1) * 9 + j];
    }
    const __half h0 = __float2half_rn(w0), h1 = __float2half_rn(w1);
    const uint16_t uh0 = *(const uint16_t*)&h0, uh1 = *(const uint16_t*)&h1;
    g_Wf2[o] = (uint32_t)uh0 | ((uint32_t)uh1 << 16);
}

// =========================================================================
// fused conv2 (HMMA fp16) + bias + spline + lad reduction.
// CTA = 2-row tile (M=256) x 120 effective oc (nt=15 pure-padding tile
// skipped: warps with ng==3 run 3 n-tiles -> 6.25% fewer MMAs, bit-identical
// output). 512 threads / 16 warps. W fragments staged in SMEM (LDS.128).
// =========================================================================
#define PLANE_B  16640                 // 130 slots * 128 B
#define WSM_OFF  66560                 // W fragments after 4 A planes
#define SMEM_TC  214016                // 66560 + 147456 (s_out 122496 reuses)

__device__ __forceinline__ float softplus_fast(float t) {
    return fmaxf(t, 0.f) + __logf(1.f + __expf(-fabsf(t)));
}

__global__ void __launch_bounds__(512, 1) conv2_fused_kernel(
    const float* __restrict__ b2,
    const float* __restrict__ xin,
    float* __restrict__ out)
{
    extern __shared__ char smem[];
    __shared__ float s_b2[128];
    __shared__ float s_wr[16];
    const uint32_t sb = smem_to_u32(smem);
    const int tid = threadIdx.x, wid = tid >> 5, lane = tid & 31;
    const int x0 = blockIdx.x * 128;
    const int y0 = blockIdx.y * 2;
    const int b  = blockIdx.z;
    const int mg = wid & 3;            // m-group (64 rows of 256)
    const int ng = wid >> 2;           // n-group (32 cols of 128)
    const int ntmax = (ng < 3) ? 4 : 3;   // skip pure-padding n-tile 15

    if (tid < 128) s_b2[tid] = (tid < PCH) ? b2[tid] : 0.f;

    // ---- stage W fragments (147456 B) into smem ----
    {
        const uint32_t wdst = sb + WSM_OFF;
        #pragma unroll
        for (int it = 0; it < 18; ++it) {
            const int g = tid + it * 512;
            cp_async16(wdst + g * 16, &g_Wf2[g * 4], 16);
        }
    }
    // ---- build 4 input-row planes (y0-1 .. y0+2) via cp.async ----
    for (int g = tid; g < 4 * 130 * 8; g += 512) {
        const int p = g / 1040, rem = g - p * 1040;
        const int s = rem >> 3, q = rem & 7;
        const int yy = y0 + p - 1, xx = x0 + s - 1;
        const bool ok = ((unsigned)yy < 256u) && ((unsigned)xx < 256u);
        const size_t px = ok ? ((size_t)(b * HH + yy) * WW + xx) : 0;
        const uint32_t sa = sb + p * PLANE_B
                          + SMEM_SWIZZLE_128B((uint32_t)(s * 128 + q * 16));
        cp_async16(sa, &g_hidF[px * 32 + q * 4], ok ? 16 : 0);
    }
    CP_COMMIT();
    CP_WAIT0();
    __syncthreads();

    float d[4][4][4];
    #pragma unroll
    for (int mt = 0; mt < 4; ++mt)
        #pragma unroll
        for (int nt = 0; nt < 4; ++nt)
            #pragma unroll
            for (int r = 0; r < 4; ++r) d[mt][nt][r] = 0.f;

    // ---- MMA phase: 36 chunks (ky*12 + kx*4 + ks), barrier-free ----
    const uint32_t planeBase = sb + (mg >> 1) * PLANE_B;   // half-row offset
    const uint32_t wBase = sb + WSM_OFF + (uint32_t)(ng * 1024 + lane * 16);
    const uint32_t mBase = (uint32_t)((mg & 1) * 64 + (lane & 15));
    const uint32_t hsel  = (uint32_t)((lane >> 4) * 16);

    #pragma unroll
    for (int chunk = 0; chunk < 36; ++chunk) {
        const int ky = chunk / 12;
        const int kx = (chunk % 12) >> 2;
        const int ks = chunk & 3;
        const uint32_t pb = planeBase + ky * PLANE_B;
        const uint32_t cb = ks * 32 + hsel;
        uint32_t ah[4][4];
        #pragma unroll
        for (int mt = 0; mt < 4; ++mt) {
            const uint32_t row = mBase + mt * 16 + kx;
            ldsm_x4(ah[mt], pb + SMEM_SWIZZLE_128B(row * 128 + cb));
        }
        uint32_t bh[4][2];
        {
            uint32_t r0[4], r1[4];
            const uint32_t wa = wBase + (uint32_t)(chunk * 4096);
            lds128(r0, wa);
            lds128(r1, wa + 512);
            bh[0][0] = r0[0]; bh[0][1] = r0[1];
            bh[1][0] = r0[2]; bh[1][1] = r0[3];
            bh[2][0] = r1[0]; bh[2][1] = r1[1];
            bh[3][0] = r1[2]; bh[3][1] = r1[3];
        }
        #pragma unroll
        for (int mt = 0; mt < 4; ++mt)
            #pragma unroll
            for (int nt4 = 0; nt4 < 4; ++nt4)
                if (nt4 < ntmax)
                    mma_f16(d[mt][nt4], ah[mt], bh[nt4]);
    }

    __syncthreads();     // all A/W consumed; reuse smem for s_out

    // ---- stage result: s_out[n=0..115][m padded 264] ----
    float* s_out = (float*)smem;
    #pragma unroll
    for (int mt = 0; mt < 4; ++mt)
        #pragma unroll
        for (int nt4 = 0; nt4 < 4; ++nt4)
            #pragma unroll
            for (int r = 0; r < 4; ++r) {
                const int m = mg * 64 + mt * 16 + (lane >> 2) + ((r >> 1) * 8);
                const int n = ng * 32 + nt4 * 8 + (lane & 3) * 2 + (r & 1);
                if (n < PCH) s_out[n * 264 + m] = d[mt][nt4][r];
            }
    __syncthreads();

    // ---- fused spline: 1024 (c,pixel) units, 2 per thread ----
    float ladsum = 0.f;
    #pragma unroll
    for (int e = 0; e < 2; ++e) {
        const int u = tid + e * 512;
        const int m = u & 255;
        const int c = u >> 8;
        const int yr = y0 + (m >> 7);
        const int xc_ = x0 + (m & 127);
        float pv[29];
        #pragma unroll
        for (int j = 0; j < 29; j++)
            pv[j] = s_out[(c * 29 + j) * 264 + m] + s_b2[c * 29 + j];

        const float xv = xin[((b * C_ + c) * HW) + yr * WW + xc_];

        float uw[10];
        #pragma unroll
        for (int j = 0; j < 10; j++) uw[j] = pv[j] * 0.125f;
        float mw = uw[0];
        #pragma unroll
        for (int j = 1; j < 10; j++) mw = fmaxf(mw, uw[j]);
        float ew[10]; float ssum = 0.f;
        #pragma unroll
        for (int j = 0; j < 10; j++) { ew[j] = __expf(uw[j] - mw); ssum += ew[j]; }
        float inv = 1.0f / ssum;
        float cw[11]; cw[0] = -1.f;
        {
            float acc = 0.f;
            #pragma unroll
            for (int j = 0; j < 10; j++) {
                float wj = fmaf(0.99f * inv, ew[j], 0.001f);
                acc += wj;
                cw[j + 1] = fmaf(2.f, acc, -1.f);
            }
        }
        cw[10] = 1.f;
        float wd[10];
        #pragma unroll
        for (int j = 0; j < 10; j++) wd[j] = cw[j + 1] - cw[j];

        float uh[10];
        #pragma unroll
        for (int j = 0; j < 10; j++) uh[j] = pv[10 + j] * 0.125f;
        float mh = uh[0];
        #pragma unroll
        for (int j = 1; j < 10; j++) mh = fmaxf(mh, uh[j]);
        float eh[10]; float hsum = 0.f;
        #pragma unroll
        for (int j = 0; j < 10; j++) { eh[j] = __expf(uh[j] - mh); hsum += eh[j]; }
        float hinv = 1.0f / hsum;
        float ch[11]; ch[0] = -1.f;
        {
            float acc = 0.f;
            #pragma unroll
            for (int j = 0; j < 10; j++) {
                float hj = fmaf(0.99f * hinv, eh[j], 0.001f);
                acc += hj;
                ch[j + 1] = fmaf(2.f, acc, -1.f);
            }
        }
        ch[10] = 1.f;
        float hd[10];
        #pragma unroll
        for (int j = 0; j < 10; j++) hd[j] = ch[j + 1] - ch[j];

        const float spc = 0.53974215f;          // log(exp(0.999)-1)
        const float dvE = 0.001f + softplus_fast(spc);
        float dv[11];
        dv[0] = dvE; dv[10] = dvE;
        #pragma unroll
        for (int j = 1; j < 10; j++) dv[j] = 0.001f + softplus_fast(pv[19 + j]);

        const float xc = fminf(fmaxf(xv, -1.f), 1.f);
        float icw = cw[0], ibw = wd[0], ich = ch[0], ihh = hd[0];
        float d0 = dv[0], d1 = dv[1];
        #pragma unroll
        for (int k = 1; k < 10; k++) {
            if (xc >= cw[k]) {
                icw = cw[k]; ibw = wd[k]; ich = ch[k]; ihh = hd[k];
                d0 = dv[k]; d1 = dv[k + 1];
            }
        }

        const float idl   = ihh / ibw;
        const float theta = (xc - icw) / ibw;
        const float th2   = theta * theta;
        const float tt    = theta * (1.f - theta);
        const float numer = ihh * (idl * th2 + d0 * tt);
        const float denom = idl + (d0 + d1 - 2.f * idl) * tt;
        const float zin   = ich + numer / denom;
        const float omt   = 1.f - theta;
        const float dnum  = idl * idl * (d1 * th2 + 2.f * idl * tt + d0 * omt * omt);
        const float ladv  = __logf(dnum) - 2.f * __logf(denom);

        const bool inside = (xv >= -1.f) && (xv <= 1.f);
        out[((b * C_ + c) * HW) + yr * WW + xc_] = inside ? zin : xv;
        ladsum += inside ? ladv : 0.f;
    }

    // ---- deterministic block reduction of ladsum ----
    #pragma unroll
    for (int off = 16; off; off >>= 1)
        ladsum += __shfl_down_sync(0xffffffffu, ladsum, off);
    if (lane == 0) s_wr[wid] = ladsum;
    __syncthreads();
    if (tid == 0) {
        float s = 0.f;
        #pragma unroll
        for (int i = 0; i < 16; i++) s += s_wr[i];
        g_partial[(b * 128 + blockIdx.y) * 2 + blockIdx.x] = s;
    }
}

// =========================================================================
__global__ void __launch_bounds__(256) reduce_kernel(float* __restrict__ out)
{
    const int b = blockIdx.x;
    const int tid = threadIdx.x;
    __shared__ double sd[256];
    sd[tid] = (double)g_partial[b * 256 + tid];
    __syncthreads();
    for (int off = 128; off; off >>= 1) {
        if (tid < off) sd[tid] += sd[tid + off];
        __syncthreads();
    }
    if (tid == 0) out[B_ * C_ * HW + b] = (float)sd[0];
}

// =========================================================================
extern "C" void kernel_launch(void* const* d_in, const int* in_sizes, int n_in,
                              void* d_out, int out_size)
{
    const float* x     = (const float*)d_in[0];
    const float* clean = (const float*)d_in[1];
    const float* W1    = (const float*)d_in[2];
    const float* b1    = (const float*)d_in[3];
    const float* W2    = (const float*)d_in[4];
    const float* b2    = (const float*)d_in[5];
    float* out = (float*)d_out;

    cudaFuncSetAttribute(conv2_fused_kernel,
                         cudaFuncAttributeMaxDynamicSharedMemorySize, SMEM_TC);

    prep_w1_kernel<<<6, 256>>>(W1);
    prep_w_kernel<<<144, 256>>>(W2);
    conv1_tc_kernel<<<dim3(2, 256, 16), 256>>>(clean, b1);
    conv2_fused_kernel<<<dim3(2, 128, 16), 512, SMEM_TC>>>(b2, x, out);
    reduce_kernel<<<16, 256>>>(out);
}

// round 17
// speedup vs baseline: 1.0630x; 1.0562x over previous
#include <cuda_runtime.h>
#include <cuda_fp16.h>
#include <cstdint>

#define B_   16
#define C_   4
#define HH   256
#define WW   256
#define HID  64
#define PCH  116          // C_*(3*10-1)
#define HW   (HH*WW)      // 65536

// ---------------- device scratch (no allocations allowed) ----------------
// hid as packed fp16x2, ic-contiguous per pixel: g_hidF[px*32 + p] = ic 2p,2p+1
__device__ __align__(16) uint32_t g_hidF[B_ * HW * 32];    // 134 MB
__device__ float g_partial[B_ * 256];
// W2 fragments, LDS.128-blocked: blk = (chunk*4+ng)*2+p, word = lane*4+h*2+w
__device__ __align__(16) uint32_t g_Wf2[288 * 128];
// W1 in mma.m16n8k8 B-fragment layout, fp16
__device__ __align__(16) uint32_t g_Wf1[6 * 8 * 32];

// ======================= helpers =====================
__device__ __forceinline__ uint32_t smem_to_u32(const void* p) {
    uint32_t a;
    asm("{ .reg .u64 t; cvta.to.shared.u64 t, %1; cvt.u32.u64 %0, t; }"
        : "=r"(a) : "l"(p));
    return a;
}
#define SMEM_SWIZZLE_128B(o) ((o) ^ (((o) >> 3) & 0x70))

__device__ __forceinline__ void cp_async16(uint32_t saddr, const void* gptr,
                                           int src_bytes) {
    asm volatile("cp.async.cg.shared.global [%0], [%1], 16, %2;"
        :: "r"(saddr), "l"(gptr), "r"(src_bytes));
}
#define CP_COMMIT() asm volatile("cp.async.commit_group;" ::: "memory")
#define CP_WAIT0()  asm volatile("cp.async.wait_group 0;" ::: "memory")

__device__ __forceinline__ void ldsm_x4(uint32_t* r, uint32_t addr) {
    asm volatile("ldmatrix.sync.aligned.m8n8.x4.shared.b16 {%0,%1,%2,%3}, [%4];"
        : "=r"(r[0]), "=r"(r[1]), "=r"(r[2]), "=r"(r[3]) : "r"(addr));
}
__device__ __forceinline__ void lds128(uint32_t* r, uint32_t addr) {
    asm volatile("ld.shared.v4.b32 {%0,%1,%2,%3}, [%4];"
        : "=r"(r[0]), "=r"(r[1]), "=r"(r[2]), "=r"(r[3]) : "r"(addr));
}
__device__ __forceinline__ void mma_f16(float* d, const uint32_t* a,
                                        const uint32_t* b) {
    asm volatile(
        "mma.sync.aligned.m16n8k16.row.col.f32.f16.f16.f32 "
        "{%0,%1,%2,%3}, {%4,%5,%6,%7}, {%8,%9}, {%0,%1,%2,%3};"
        : "+f"(d[0]), "+f"(d[1]), "+f"(d[2]), "+f"(d[3])
        : "r"(a[0]), "r"(a[1]), "r"(a[2]), "r"(a[3]),
          "r"(b[0]), "r"(b[1]));
}
__device__ __forceinline__ void mma_f16_k8(float* d, const uint32_t* a,
                                           uint32_t b) {
    asm volatile(
        "mma.sync.aligned.m16n8k8.row.col.f32.f16.f16.f32 "
        "{%0,%1,%2,%3}, {%4,%5}, {%6}, {%0,%1,%2,%3};"
        : "+f"(d[0]), "+f"(d[1]), "+f"(d[2]), "+f"(d[3])
        : "r"(a[0]), "r"(a[1]), "r"(b));
}

// =========================================================================
// prep_w1: pack W1 into m16n8k8 B-fragment layout, fp16.
// =========================================================================
__global__ void __launch_bounds__(256) prep_w1_kernel(const float* __restrict__ W1)
{
    const int i = blockIdx.x * 256 + threadIdx.x;
    if (i >= 6 * 8 * 32) return;
    const int lane  = i & 31;
    const int nt    = (i >> 5) & 7;
    const int chunk = i >> 8;
    const int ky = chunk >> 1, cb = chunk & 1;
    const int n  = nt * 8 + (lane >> 2);
    const int k0 = (lane & 3) * 2;

    float w[2];
    #pragma unroll
    for (int e = 0; e < 2; ++e) {
        const int ke = k0 + e;
        const int p = ke >> 2, ic = ke & 3;
        const int kx = cb ? (2 + p) : p;
        w[e] = (kx < 3) ? W1[n * 36 + ic * 9 + ky * 3 + kx] : 0.f;
    }
    const __half2 h = __floats2half2_rn(w[0], w[1]);
    g_Wf1[i] = *(const uint32_t*)&h;
}

// =========================================================================
// conv1 via HMMA fp16: clean -> relu(conv3x3) -> g_hidF (packed fp16).
// =========================================================================
__global__ void __launch_bounds__(256) conv1_tc_kernel(
    const float* __restrict__ clean,
    const float* __restrict__ b1)
{
    __shared__ uint2 s_cl[3][132];
    __shared__ float s_b1[64];
    const int tid = threadIdx.x, wid = tid >> 5, lane = tid & 31;
    const int x0 = blockIdx.x * 128;
    const int y  = blockIdx.y;
    const int b  = blockIdx.z;
    const int mg = wid & 3;
    const int ng = wid >> 2;

    if (tid < 64) s_b1[tid] = b1[tid];
    for (int i = tid; i < 3 * 131; i += 256) {
        const int ky = i / 131, s = i - ky * 131;
        const int yy = y + ky - 1, xx = x0 + s - 1;
        uint2 v = make_uint2(0, 0);
        if ((unsigned)yy < 256u && (unsigned)xx < 256u) {
            const int base = (b * 4) * HW + yy * WW + xx;
            const float c0 = clean[base];
            const float c1 = clean[base + HW];
            const float c2 = clean[base + 2 * HW];
            const float c3 = clean[base + 3 * HW];
            const __half2 h01 = __floats2half2_rn(c0, c1);
            const __half2 h23 = __floats2half2_rn(c2, c3);
            v.x = *(const uint32_t*)&h01;
            v.y = *(const uint32_t*)&h23;
        }
        s_cl[ky][s] = v;
    }
    __syncthreads();

    float d[2][4][4];
    #pragma unroll
    for (int mt = 0; mt < 2; ++mt)
        #pragma unroll
        for (int nt = 0; nt < 4; ++nt)
            #pragma unroll
            for (int r = 0; r < 4; ++r) d[mt][nt][r] = 0.f;

    const uint32_t sbcl = smem_to_u32(&s_cl[0][0]);
    const int q = lane & 3;
    #pragma unroll
    for (int chunk = 0; chunk < 6; ++chunk) {
        const int ky = chunk >> 1, cb = chunk & 1;
        const int so = (cb ? 2 : 0) + (q >> 1);
        uint32_t a[2][2];
        #pragma unroll
        for (int mt = 0; mt < 2; ++mt) {
            const int row = mg * 32 + mt * 16 + (lane >> 2);
            const uint32_t ad = sbcl + (uint32_t)((ky * 132 + row + so) * 8 + (q & 1) * 4);
            asm volatile("ld.shared.b32 %0, [%1];" : "=r"(a[mt][0]) : "r"(ad));
            asm volatile("ld.shared.b32 %0, [%1];" : "=r"(a[mt][1]) : "r"(ad + 64));
        }
        #pragma unroll
        for (int nt = 0; nt < 4; ++nt) {
            const uint32_t bw = g_Wf1[(chunk * 8 + ng * 4 + nt) * 32 + lane];
            #pragma unroll
            for (int mt = 0; mt < 2; ++mt)
                mma_f16_k8(d[mt][nt], a[mt], bw);
        }
    }

    #pragma unroll
    for (int mt = 0; mt < 2; ++mt) {
        const int r0 = mg * 32 + mt * 16 + (lane >> 2);
        const size_t px0 = (size_t)(b * HH + y) * WW + x0 + r0;
        #pragma unroll
        for (int nt = 0; nt < 4; ++nt) {
            const int col = ng * 32 + nt * 8 + (lane & 3) * 2;
            const float bb0 = s_b1[col], bb1 = s_b1[col + 1];
            const __half2 h0 = __floats2half2_rn(fmaxf(d[mt][nt][0] + bb0, 0.f),
                                                 fmaxf(d[mt][nt][1] + bb1, 0.f));
            const __half2 h1 = __floats2half2_rn(fmaxf(d[mt][nt][2] + bb0, 0.f),
                                                 fmaxf(d[mt][nt][3] + bb1, 0.f));
            const int word = col >> 1;
            g_hidF[px0 * 32 + word]       = *(const uint32_t*)&h0;
            g_hidF[(px0 + 8) * 32 + word] = *(const uint32_t*)&h1;
        }
    }
}

// =========================================================================
// prep_w: pack W2 into LDS.128-blocked mma B-fragment layout, fp16.
// =========================================================================
__global__ void __launch_bounds__(256) prep_w_kernel(const float* __restrict__ W2)
{
    const int o = blockIdx.x * 256 + threadIdx.x;
    if (o >= 288 * 128) return;
    const int w    = o & 1;
    const int h    = (o >> 1) & 1;
    const int lane = (o >> 2) & 31;
    const int blk  = o >> 7;
    const int p    = blk & 1;
    const int ngc  = blk >> 1;
    const int ng   = ngc & 3;
    const int chunk = ngc >> 2;        // 0..35 = j*4+ks
    const int j    = chunk >> 2;
    const int ks   = chunk & 3;
    const int nt   = ng * 4 + p * 2 + h;
    const int n    = nt * 8 + (lane >> 2);
    const int ic0  = ks * 16 + w * 8 + (lane & 3) * 2;

    float w0 = 0.f, w1 = 0.f;
    if (n < PCH) {
        w0 = W2[n * 576 + ic0 * 9 + j];
        w1 = W2[n * 576 + (ic0 + 1) * 9 + j];
    }
    const __half h0 = __float2half_rn(w0), h1 = __float2half_rn(w1);
    const uint16_t uh0 = *(const uint16_t*)&h0, uh1 = *(const uint16_t*)&h1;
    g_Wf2[o] = (uint32_t)uh0 | ((uint32_t)uh1 << 16);
}

// =========================================================================
// MMA phase, templated on n-tile count (warp-uniform, compile-time).
// NT=4 for ng 0..2; NT=3 for ng 3 (tile 15 = cols 120..127 pure padding).
// =========================================================================
template<int NT>
__device__ __forceinline__ void run_mma_phase(
    float (&d)[4][4][4],
    uint32_t planeBase, uint32_t wBase, uint32_t mBase, uint32_t hsel)
{
    #pragma unroll
    for (int chunk = 0; chunk < 36; ++chunk) {
        const int ky = chunk / 12;
        const int kx = (chunk % 12) >> 2;
        const int ks = chunk & 3;
        const uint32_t pb = planeBase + ky * 16640;
        const uint32_t cb = ks * 32 + hsel;
        uint32_t ah[4][4];
        #pragma unroll
        for (int mt = 0; mt < 4; ++mt) {
            const uint32_t row = mBase + mt * 16 + kx;
            ldsm_x4(ah[mt], pb + SMEM_SWIZZLE_128B(row * 128 + cb));
        }
        uint32_t bh[4][2];
        {
            uint32_t r0[4], r1[4];
            const uint32_t wa = wBase + (uint32_t)(chunk * 4096);
            lds128(r0, wa);
            lds128(r1, wa + 512);
            bh[0][0] = r0[0]; bh[0][1] = r0[1];
            bh[1][0] = r0[2]; bh[1][1] = r0[3];
            bh[2][0] = r1[0]; bh[2][1] = r1[1];
            bh[3][0] = r1[2]; bh[3][1] = r1[3];
        }
        #pragma unroll
        for (int mt = 0; mt < 4; ++mt)
            #pragma unroll
            for (int nt4 = 0; nt4 < NT; ++nt4)
                mma_f16(d[mt][nt4], ah[mt], bh[nt4]);
    }
}

// =========================================================================
// fused conv2 (HMMA fp16) + bias + spline + lad reduction.
// CTA = 2-row tile (M=256) x 128 oc padded; warp ng==3 skips padding tile 15
// via compile-time-specialized loop. 512 threads / 16 warps. W in SMEM.
// =========================================================================
#define PLANE_B  16640                 // 130 slots * 128 B
#define WSM_OFF  66560                 // W fragments after 4 A planes
#define SMEM_TC  214016                // 66560 + 147456 (s_out 122496 reuses)

__device__ __forceinline__ float softplus_fast(float t) {
    return fmaxf(t, 0.f) + __logf(1.f + __expf(-fabsf(t)));
}

__global__ void __launch_bounds__(512, 1) conv2_fused_kernel(
    const float* __restrict__ b2,
    const float* __restrict__ xin,
    float* __restrict__ out)
{
    extern __shared__ char smem[];
    __shared__ float s_b2[128];
    __shared__ float s_wr[16];
    const uint32_t sb = smem_to_u32(smem);
    const int tid = threadIdx.x, wid = tid >> 5, lane = tid & 31;
    const int x0 = blockIdx.x * 128;
    const int y0 = blockIdx.y * 2;
    const int b  = blockIdx.z;
    const int mg = wid & 3;            // m-group (64 rows of 256)
    const int ng = wid >> 2;           // n-group (32 cols of 128)

    if (tid < 128) s_b2[tid] = (tid < PCH) ? b2[tid] : 0.f;

    // ---- stage W fragments (147456 B) into smem ----
    {
        const uint32_t wdst = sb + WSM_OFF;
        #pragma unroll
        for (int it = 0; it < 18; ++it) {
            const int g = tid + it * 512;
            cp_async16(wdst + g * 16, &g_Wf2[g * 4], 16);
        }
    }
    // ---- build 4 input-row planes (y0-1 .. y0+2) via cp.async ----
    for (int g = tid; g < 4 * 130 * 8; g += 512) {
        const int p = g / 1040, rem = g - p * 1040;
        const int s = rem >> 3, q = rem & 7;
        const int yy = y0 + p - 1, xx = x0 + s - 1;
        const bool ok = ((unsigned)yy < 256u) && ((unsigned)xx < 256u);
        const size_t px = ok ? ((size_t)(b * HH + yy) * WW + xx) : 0;
        const uint32_t sa = sb + p * PLANE_B
                          + SMEM_SWIZZLE_128B((uint32_t)(s * 128 + q * 16));
        cp_async16(sa, &g_hidF[px * 32 + q * 4], ok ? 16 : 0);
    }
    CP_COMMIT();
    CP_WAIT0();
    __syncthreads();

    float d[4][4][4];
    #pragma unroll
    for (int mt = 0; mt < 4; ++mt)
        #pragma unroll
        for (int nt = 0; nt < 4; ++nt)
            #pragma unroll
            for (int r = 0; r < 4; ++r) d[mt][nt][r] = 0.f;

    // ---- MMA phase (warp-uniform specialization on padding skip) ----
    const uint32_t planeBase = sb + (mg >> 1) * PLANE_B;   // half-row offset
    const uint32_t wBase = sb + WSM_OFF + (uint32_t)(ng * 1024 + lane * 16);
    const uint32_t mBase = (uint32_t)((mg & 1) * 64 + (lane & 15));
    const uint32_t hsel  = (uint32_t)((lane >> 4) * 16);

    if (ng < 3) run_mma_phase<4>(d, planeBase, wBase, mBase, hsel);
    else        run_mma_phase<3>(d, planeBase, wBase, mBase, hsel);

    __syncthreads();     // all A/W consumed; reuse smem for s_out

    // ---- stage result: s_out[n=0..115][m padded 264] ----
    float* s_out = (float*)smem;
    #pragma unroll
    for (int mt = 0; mt < 4; ++mt)
        #pragma unroll
        for (int nt4 = 0; nt4 < 4; ++nt4)
            #pragma unroll
            for (int r = 0; r < 4; ++r) {
                const int m = mg * 64 + mt * 16 + (lane >> 2) + ((r >> 1) * 8);
                const int n = ng * 32 + nt4 * 8 + (lane & 3) * 2 + (r & 1);
                if (n < PCH) s_out[n * 264 + m] = d[mt][nt4][r];
            }
    __syncthreads();

    // ---- fused spline: 1024 (c,pixel) units, 2 per thread ----
    float ladsum = 0.f;
    #pragma unroll
    for (int e = 0; e < 2; ++e) {
        const int u = tid + e * 512;
        const int m = u & 255;
        const int c = u >> 8;
        const int yr = y0 + (m >> 7);
        const int xc_ = x0 + (m & 127);
        float pv[29];
        #pragma unroll
        for (int j = 0; j < 29; j++)
            pv[j] = s_out[(c * 29 + j) * 264 + m] + s_b2[c * 29 + j];

        const float xv = xin[((b * C_ + c) * HW) + yr * WW + xc_];

        float uw[10];
        #pragma unroll
        for (int j = 0; j < 10; j++) uw[j] = pv[j] * 0.125f;
        float mw = uw[0];
        #pragma unroll
        for (int j = 1; j < 10; j++) mw = fmaxf(mw, uw[j]);
        float ew[10]; float ssum = 0.f;
        #pragma unroll
        for (int j = 0; j < 10; j++) { ew[j] = __expf(uw[j] - mw); ssum += ew[j]; }
        float inv = 1.0f / ssum;
        float cw[11]; cw[0] = -1.f;
        {
            float acc = 0.f;
            #pragma unroll
            for (int j = 0; j < 10; j++) {
                float wj = fmaf(0.99f * inv, ew[j], 0.001f);
                acc += wj;
                cw[j + 1] = fmaf(2.f, acc, -1.f);
            }
        }
        cw[10] = 1.f;
        float wd[10];
        #pragma unroll
        for (int j = 0; j < 10; j++) wd[j] = cw[j + 1] - cw[j];

        float uh[10];
        #pragma unroll
        for (int j = 0; j < 10; j++) uh[j] = pv[10 + j] * 0.125f;
        float mh = uh[0];
        #pragma unroll
        for (int j = 1; j < 10; j++) mh = fmaxf(mh, uh[j]);
        float eh[10]; float hsum = 0.f;
        #pragma unroll
        for (int j = 0; j < 10; j++) { eh[j] = __expf(uh[j] - mh); hsum += eh[j]; }
        float hinv = 1.0f / hsum;
        float ch[11]; ch[0] = -1.f;
        {
            float acc = 0.f;
            #pragma unroll
            for (int j = 0; j < 10; j++) {
                float hj = fmaf(0.99f * hinv, eh[j], 0.001f);
                acc += hj;
                ch[j + 1] = fmaf(2.f, acc, -1.f);
            }
        }
        ch[10] = 1.f;
        float hd[10];
        #pragma unroll
        for (int j = 0; j < 10; j++) hd[j] = ch[j + 1] - ch[j];

        const float spc = 0.53974215f;          // log(exp(0.999)-1)
        const float dvE = 0.001f + softplus_fast(spc);
        float dv[11];
        dv[0] = dvE; dv[10] = dvE;
        #pragma unroll
        for (int j = 1; j < 10; j++) dv[j] = 0.001f + softplus_fast(pv[19 + j]);

        const float xc = fminf(fmaxf(xv, -1.f), 1.f);
        float icw = cw[0], ibw = wd[0], ich = ch[0], ihh = hd[0];
        float d0 = dv[0], d1 = dv[1];
        #pragma unroll
        for (int k = 1; k < 10; k++) {
            if (xc >= cw[k]) {
                icw = cw[k]; ibw = wd[k]; ich = ch[k]; ihh = hd[k];
                d0 = dv[k]; d1 = dv[k + 1];
            }
        }

        const float idl   = ihh / ibw;
        const float theta = (xc - icw) / ibw;
        const float th2   = theta * theta;
        const float tt    = theta * (1.f - theta);
        const float numer = ihh * (idl * th2 + d0 * tt);
        const float denom = idl + (d0 + d1 - 2.f * idl) * tt;
        const float zin   = ich + numer / denom;
        const float omt   = 1.f - theta;
        const float dnum  = idl * idl * (d1 * th2 + 2.f * idl * tt + d0 * omt * omt);
        const float ladv  = __logf(dnum) - 2.f * __logf(denom);

        const bool inside = (xv >= -1.f) && (xv <= 1.f);
        out[((b * C_ + c) * HW) + yr * WW + xc_] = inside ? zin : xv;
        ladsum += inside ? ladv : 0.f;
    }

    // ---- deterministic block reduction of ladsum ----
    #pragma unroll
    for (int off = 16; off; off >>= 1)
        ladsum += __shfl_down_sync(0xffffffffu, ladsum, off);
    if (lane == 0) s_wr[wid] = ladsum;
    __syncthreads();
    if (tid == 0) {
        float s = 0.f;
        #pragma unroll
        for (int i = 0; i < 16; i++) s += s_wr[i];
        g_partial[(b * 128 + blockIdx.y) * 2 + blockIdx.x] = s;
    }
}

// =========================================================================
__global__ void __launch_bounds__(256) reduce_kernel(float* __restrict__ out)
{
    const int b = blockIdx.x;
    const int tid = threadIdx.x;
    __shared__ double sd[256];
    sd[tid] = (double)g_partial[b * 256 + tid];
    __syncthreads();
    for (int off = 128; off; off >>= 1) {
        if (tid < off) sd[tid] += sd[tid + off];
        __syncthreads();
    }
    if (tid == 0) out[B_ * C_ * HW + b] = (float)sd[0];
}

// =========================================================================
extern "C" void kernel_launch(void* const* d_in, const int* in_sizes, int n_in,
                              void* d_out, int out_size)
{
    const float* x     = (const float*)d_in[0];
    const float* clean = (const float*)d_in[1];
    const float* W1    = (const float*)d_in[2];
    const float* b1    = (const float*)d_in[3];
    const float* W2    = (const float*)d_in[4];
    const float* b2    = (const float*)d_in[5];
    float* out = (float*)d_out;

    cudaFuncSetAttribute(conv2_fused_kernel,
                         cudaFuncAttributeMaxDynamicSharedMemorySize, SMEM_TC);

    prep_w1_kernel<<<6, 256>>>(W1);
    prep_w_kernel<<<144, 256>>>(W2);
    conv1_tc_kernel<<<dim3(2, 256, 16), 256>>>(clean, b1);
    conv2_fused_kernel<<<dim3(2, 128, 16), 512, SMEM_TC>>>(b2, x, out);
    reduce_kernel<<<16, 256>>>(out);
}